// round 1
// baseline (speedup 1.0000x reference)
#include <cuda_runtime.h>
#include <cuda_bf16.h>
#include <math_constants.h>

// Problem constants
#define NB    2048      // queries
#define NP    100000    // data points
#define DD    64        // dim
#define KK    20        // top-k
#define HH    256       // hidden
#define ZLD   66        // z row stride (D+2)

// KNN pass-1 tiling
#define NCH   128       // point chunks
#define CHUNK 782       // ceil(100000/128)
#define KEEP  7         // candidates kept per (query, chunk)
#define TS    64        // shared tile points
#define P1T   128       // threads per pass-1 block (queries per block)

// Scratch (device globals; no allocation allowed)
__device__ float    g_pn2[NP];
__device__ unsigned g_keys[(size_t)NB * NCH * KEEP];

// ---------------------------------------------------------------------------
// Kernel 0: per-point squared norms
// ---------------------------------------------------------------------------
__global__ void pn2_kernel(const float* __restrict__ data) {
    int i = blockIdx.x * 256 + threadIdx.x;
    if (i >= NP) return;
    const float4* r = (const float4*)(data + (size_t)i * DD);
    float s = 0.f;
#pragma unroll
    for (int k = 0; k < 16; k++) {
        float4 v = r[k];
        s = fmaf(v.x, v.x, s);
        s = fmaf(v.y, v.y, s);
        s = fmaf(v.z, v.z, s);
        s = fmaf(v.w, v.w, s);
    }
    g_pn2[i] = s;
}

// ---------------------------------------------------------------------------
// Kernel 1: MLP  x_dot = relu([x,t]@W1+b1)@W2+b2  -> out cols [0,64)
// 8 queries per block to reuse W1/W2 loads.
// ---------------------------------------------------------------------------
__global__ __launch_bounds__(256) void mlp_kernel(
    const float* __restrict__ z, const float* __restrict__ t,
    const float* __restrict__ W1, const float* __restrict__ b1,
    const float* __restrict__ W2, const float* __restrict__ b2,
    float* __restrict__ out)
{
    __shared__ float sin[8][65];
    __shared__ float sh[8][256];
    int qb = blockIdx.x * 8;
    int tid = threadIdx.x;

    for (int i = tid; i < 8 * 64; i += 256)
        sin[i >> 6][i & 63] = z[(size_t)(qb + (i >> 6)) * ZLD + (i & 63)];
    if (tid < 8) sin[tid][64] = t[0];
    __syncthreads();

    float acc[8];
#pragma unroll
    for (int i = 0; i < 8; i++) acc[i] = b1[tid];
    for (int d = 0; d < 65; d++) {
        float w = W1[d * 256 + tid];
#pragma unroll
        for (int i = 0; i < 8; i++) acc[i] = fmaf(sin[i][d], w, acc[i]);
    }
#pragma unroll
    for (int i = 0; i < 8; i++) sh[i][tid] = fmaxf(acc[i], 0.f);
    __syncthreads();

#pragma unroll
    for (int rep = 0; rep < 2; rep++) {
        int qi = rep * 4 + (tid >> 6);
        int d  = tid & 63;
        float o = b2[d];
        for (int j = 0; j < 256; j++) o = fmaf(sh[qi][j], W2[j * 64 + d], o);
        out[(size_t)(qb + qi) * ZLD + d] = o;
    }
}

// ---------------------------------------------------------------------------
// Kernel 2: KNN pass 1 — per (query, chunk) keep top-KEEP packed keys.
// Key = (float bits of d^2, low 11 bits replaced by local point index).
// d^2 >= 0 so float bits are monotone as unsigned.
// ---------------------------------------------------------------------------
__global__ __launch_bounds__(P1T) void knn_pass1(
    const float* __restrict__ z, const float* __restrict__ data)
{
    __shared__ float sP[TS * DD];
    __shared__ float sN[TS];

    int tid   = threadIdx.x;
    int q     = blockIdx.x * P1T + tid;
    int chunk = blockIdx.y;
    int cs    = chunk * CHUNK;
    int ce    = min(cs + CHUNK, NP);

    // query into registers (row stride 66 floats -> 8B aligned, use float2)
    float qv[DD];
    const float2* zr = (const float2*)(z + (size_t)q * ZLD);
#pragma unroll
    for (int i = 0; i < 32; i++) {
        float2 v = zr[i];
        qv[2 * i]     = v.x;
        qv[2 * i + 1] = v.y;
    }
    float qn2 = 0.f;
#pragma unroll
    for (int d = 0; d < DD; d++) qn2 = fmaf(qv[d], qv[d], qn2);

    unsigned keys[KEEP];
#pragma unroll
    for (int i = 0; i < KEEP; i++) keys[i] = 0xFFFFFFFFu;

    for (int t0 = cs; t0 < ce; t0 += TS) {
        int cnt = min(TS, ce - t0);
        __syncthreads();
        {
            const float4* src = (const float4*)(data + (size_t)t0 * DD);
            float4* dst = (float4*)sP;
            for (int i = tid; i < cnt * 16; i += P1T) dst[i] = src[i];
            for (int i = tid; i < cnt; i += P1T) sN[i] = g_pn2[t0 + i];
        }
        __syncthreads();

        int lbase = t0 - cs;
        for (int j = 0; j < cnt; j++) {
            float s0 = qn2 + sN[j];
            const float4* p4 = (const float4*)(sP + j * DD);
            float a0 = 0.f, a1 = 0.f, a2 = 0.f, a3 = 0.f;
#pragma unroll
            for (int i = 0; i < 16; i++) {
                float4 p = p4[i];
                a0 = fmaf(qv[4 * i],     p.x, a0);
                a1 = fmaf(qv[4 * i + 1], p.y, a1);
                a2 = fmaf(qv[4 * i + 2], p.z, a2);
                a3 = fmaf(qv[4 * i + 3], p.w, a3);
            }
            float dot = (a0 + a1) + (a2 + a3);
            float d2  = fmaf(-2.f, dot, s0);
            d2 = fmaxf(d2, 0.f);
            unsigned key = (__float_as_uint(d2) & 0xFFFFF800u) |
                           (unsigned)(lbase + j);
            if (key < keys[KEEP - 1]) {
                // insert into sorted ascending list (min/max network, 2 ops/level)
#pragma unroll
                for (int i = KEEP - 1; i >= 1; --i)
                    keys[i] = max(keys[i - 1], min(keys[i], key));
                keys[0] = min(keys[0], key);
            }
        }
    }

    unsigned* outk = g_keys + ((size_t)q * NCH + chunk) * KEEP;
#pragma unroll
    for (int i = 0; i < KEEP; i++) outk[i] = keys[i];
}

// ---------------------------------------------------------------------------
// Kernel 3: pass 2 — exact rescore of NCH*KEEP candidates, exact top-20,
// weights, u_t, cos_sim + L2 -> out cols 64,65.
// ---------------------------------------------------------------------------
#define CAND (NCH * KEEP)   // 896
__global__ __launch_bounds__(256) void knn_pass2(
    const float* __restrict__ z, const float* __restrict__ data,
    const float* __restrict__ vel, float* __restrict__ out)
{
    __shared__ float sq[DD];
    __shared__ float scd[CAND];
    __shared__ int   sci[CAND];
    __shared__ unsigned long long sred[8];
    __shared__ unsigned long long s_best;
    __shared__ unsigned long long selkey[KK];
    __shared__ float sdist[KK];
    __shared__ float sw[KK];
    __shared__ int   sidx20[KK];
    __shared__ float swsum;
    __shared__ float pr_ux[DD], pr_uu[DD], pr_xx[DD], pr_l2[DD];

    int q = blockIdx.x;
    int tid = threadIdx.x;

    if (tid < DD) sq[tid] = z[(size_t)q * ZLD + tid];
    __syncthreads();

    float qn2 = 0.f;
#pragma unroll
    for (int d = 0; d < DD; d++) qn2 = fmaf(sq[d], sq[d], qn2);

    // exact d^2 for all candidates
    for (int c = tid; c < CAND; c += 256) {
        int chunk = c / KEEP;
        unsigned key = g_keys[((size_t)q * NCH + chunk) * KEEP + (c % KEEP)];
        int gidx = chunk * CHUNK + (int)(key & 0x7FFu);
        const float4* row = (const float4*)(data + (size_t)gidx * DD);
        float a0 = 0.f, a1 = 0.f, a2 = 0.f, a3 = 0.f;
#pragma unroll
        for (int i = 0; i < 16; i++) {
            float4 p = row[i];
            a0 = fmaf(sq[4 * i],     p.x, a0);
            a1 = fmaf(sq[4 * i + 1], p.y, a1);
            a2 = fmaf(sq[4 * i + 2], p.z, a2);
            a3 = fmaf(sq[4 * i + 3], p.w, a3);
        }
        float dot = (a0 + a1) + (a2 + a3);
        float d2 = qn2 + g_pn2[gidx] - 2.f * dot;
        scd[c] = fmaxf(d2, 0.f);
        sci[c] = gidx;
    }
    __syncthreads();

    // exact top-20, tie-break by smallest global index (lax.top_k semantics)
    for (int r = 0; r < KK; r++) {
        unsigned long long best = ~0ULL;
        for (int c = tid; c < CAND; c += 256) {
            unsigned long long k =
                ((unsigned long long)__float_as_uint(scd[c]) << 32) |
                (unsigned)sci[c];
            best = min(best, k);
        }
#pragma unroll
        for (int o = 16; o > 0; o >>= 1)
            best = min(best, __shfl_down_sync(0xffffffffu, best, o));
        if ((tid & 31) == 0) sred[tid >> 5] = best;
        __syncthreads();
        if (tid == 0) {
            unsigned long long b = sred[0];
#pragma unroll
            for (int w = 1; w < 8; w++) b = min(b, sred[w]);
            selkey[r] = b;
            s_best = b;
        }
        __syncthreads();
        unsigned long long bk = s_best;
        for (int c = tid; c < CAND; c += 256) {
            unsigned long long k =
                ((unsigned long long)__float_as_uint(scd[c]) << 32) |
                (unsigned)sci[c];
            if (k == bk) scd[c] = CUDART_INF_F;
        }
        __syncthreads();
    }

    // weights
    if (tid < KK) {
        unsigned long long k = selkey[tid];
        float d2v = __uint_as_float((unsigned)(k >> 32));
        sidx20[tid] = (int)(k & 0xFFFFFFFFu);
        sdist[tid]  = sqrtf(fmaxf(d2v, 1e-30f));
    }
    __syncthreads();
    float h = fmaxf(sdist[KK - 1], 1e-12f);
    if (tid < KK)
        sw[tid] = expf(-(sdist[tid] * sdist[tid]) / (2.f * h * h));
    __syncthreads();
    if (tid == 0) {
        float s = 0.f;
        for (int i = 0; i < KK; i++) s += sw[i];
        swsum = s + 1e-12f;
    }
    __syncthreads();

    // u_t and metric partials
    if (tid < DD) {
        float u = 0.f;
#pragma unroll
        for (int i = 0; i < KK; i++)
            u = fmaf(sw[i], vel[(size_t)sidx20[i] * DD + tid], u);
        u *= (1.f / swsum);
        float xd = out[(size_t)q * ZLD + tid];
        pr_ux[tid] = u * xd;
        pr_uu[tid] = u * u;
        pr_xx[tid] = xd * xd;
        float dfe = u - xd;
        pr_l2[tid] = dfe * dfe;
    }
    __syncthreads();
    if (tid == 0) {
        float ux = 0.f, uu = 0.f, xx = 0.f, l2 = 0.f;
        for (int d = 0; d < DD; d++) {
            ux += pr_ux[d]; uu += pr_uu[d]; xx += pr_xx[d]; l2 += pr_l2[d];
        }
        float nu = fmaxf(sqrtf(uu), 1e-8f);
        float nx = fmaxf(sqrtf(xx), 1e-8f);
        out[(size_t)q * ZLD + 64] = 1.f - ux / (nu * nx);
        out[(size_t)q * ZLD + 65] = l2;
    }
}

// ---------------------------------------------------------------------------
extern "C" void kernel_launch(void* const* d_in, const int* in_sizes, int n_in,
                              void* d_out, int out_size)
{
    const float* t    = (const float*)d_in[0];
    const float* z    = (const float*)d_in[1];
    const float* data = (const float*)d_in[2];
    const float* vel  = (const float*)d_in[3];
    const float* W1   = (const float*)d_in[4];
    const float* b1   = (const float*)d_in[5];
    const float* W2   = (const float*)d_in[6];
    const float* b2   = (const float*)d_in[7];
    float* out = (float*)d_out;

    pn2_kernel<<<(NP + 255) / 256, 256>>>(data);
    mlp_kernel<<<NB / 8, 256>>>(z, t, W1, b1, W2, b2, out);
    knn_pass1<<<dim3(NB / P1T, NCH), P1T>>>(z, data);
    knn_pass2<<<NB, 256>>>(z, data, vel, out);
}

// round 3
// speedup vs baseline: 1.1894x; 1.1894x over previous
#include <cuda_runtime.h>
#include <cuda_bf16.h>
#include <math_constants.h>

// Problem constants
#define NB    2048      // queries
#define NP    100000    // data points
#define DD    64        // dim
#define KK    20        // top-k
#define ZLD   66        // z row stride (D+2)

// KNN pass-1 tiling
#define NCH   128       // point chunks
#define CHUNK 784       // points per chunk (multiple of 16)
#define KEEP  7         // candidates kept per (query, chunk)
#define TS    64        // shared tile points
#define P1T   128       // threads per pass-1 block (queries per block)
#define PADP  100416    // padded point count (covers 127*784+832, mult of 64)
#define CAND  (NCH * KEEP)   // 896

// Scratch (device globals; no allocation allowed)
__device__ float              g_pn2[PADP];
__device__ float              g_dataT[(size_t)DD * PADP];          // dim-major, zero-padded
__device__ unsigned long long g_cand[(size_t)NB * CAND];          // (d2bits<<32)|gidx

// packed f32x2 helpers
#define FMA2(acc, a, b) asm("fma.rn.f32x2 %0, %1, %2, %0;" : "+l"(acc) : "l"(a), "l"(b))
#define PACK2(d, x, y)  asm("mov.b64 %0, {%1, %2};" : "=l"(d) : "f"(x), "f"(y))
#define UNPK2(lo, hi, v) asm("mov.b64 {%0, %1}, %2;" : "=f"(lo), "=f"(hi) : "l"(v))

// ---------------------------------------------------------------------------
// Kernel T: transpose data [NP][64] -> g_dataT [64][PADP] (zero padded)
// ---------------------------------------------------------------------------
__global__ __launch_bounds__(256) void tr_kernel(const float* __restrict__ data) {
    __shared__ float st[64 * 65];
    int p0 = blockIdx.x * 64;
    int tid = threadIdx.x;
    // load 64 points x 64 dims (coalesced float4), store point-major padded rows
    for (int idx = tid; idx < 64 * 16; idx += 256) {
        int j = idx >> 4, g = idx & 15;
        int p = p0 + j;
        float4 v = make_float4(0.f, 0.f, 0.f, 0.f);
        if (p < NP) v = ((const float4*)(data + (size_t)p * DD))[g];
        st[j * 65 + 4 * g + 0] = v.x;
        st[j * 65 + 4 * g + 1] = v.y;
        st[j * 65 + 4 * g + 2] = v.z;
        st[j * 65 + 4 * g + 3] = v.w;
    }
    __syncthreads();
    // write dim-major (coalesced, conflict-free shared reads)
    for (int idx = tid; idx < 64 * 64; idx += 256) {
        int d = idx >> 6, j = idx & 63;
        g_dataT[(size_t)d * PADP + p0 + j] = st[j * 65 + d];
    }
}

// ---------------------------------------------------------------------------
// Kernel 0: per-point squared norms (+INF for padding)
// ---------------------------------------------------------------------------
__global__ void pn2_kernel(const float* __restrict__ data) {
    int i = blockIdx.x * 256 + threadIdx.x;
    if (i >= PADP) return;
    if (i >= NP) { g_pn2[i] = CUDART_INF_F; return; }
    const float4* r = (const float4*)(data + (size_t)i * DD);
    float s = 0.f;
#pragma unroll
    for (int k = 0; k < 16; k++) {
        float4 v = r[k];
        s = fmaf(v.x, v.x, s);
        s = fmaf(v.y, v.y, s);
        s = fmaf(v.z, v.z, s);
        s = fmaf(v.w, v.w, s);
    }
    g_pn2[i] = s;
}

// ---------------------------------------------------------------------------
// Kernel 1: MLP  x_dot = relu([x,t]@W1+b1)@W2+b2  -> out cols [0,64)
// ---------------------------------------------------------------------------
__global__ __launch_bounds__(256) void mlp_kernel(
    const float* __restrict__ z, const float* __restrict__ t,
    const float* __restrict__ W1, const float* __restrict__ b1,
    const float* __restrict__ W2, const float* __restrict__ b2,
    float* __restrict__ out)
{
    __shared__ float sin_[8][65];
    __shared__ float sh[8][256];
    int qb = blockIdx.x * 8;
    int tid = threadIdx.x;

    for (int i = tid; i < 8 * 64; i += 256)
        sin_[i >> 6][i & 63] = z[(size_t)(qb + (i >> 6)) * ZLD + (i & 63)];
    if (tid < 8) sin_[tid][64] = t[0];
    __syncthreads();

    float acc[8];
#pragma unroll
    for (int i = 0; i < 8; i++) acc[i] = b1[tid];
    for (int d = 0; d < 65; d++) {
        float w = W1[d * 256 + tid];
#pragma unroll
        for (int i = 0; i < 8; i++) acc[i] = fmaf(sin_[i][d], w, acc[i]);
    }
#pragma unroll
    for (int i = 0; i < 8; i++) sh[i][tid] = fmaxf(acc[i], 0.f);
    __syncthreads();

#pragma unroll
    for (int rep = 0; rep < 2; rep++) {
        int qi = rep * 4 + (tid >> 6);
        int d  = tid & 63;
        float o = b2[d];
        for (int j = 0; j < 256; j++) o = fmaf(sh[qi][j], W2[j * 64 + d], o);
        out[(size_t)(qb + qi) * ZLD + d] = o;
    }
}

// ---------------------------------------------------------------------------
// Kernel 2: KNN pass 1 — packed f32x2 distances; per (query, chunk) keep
// top-KEEP with exact d2 payload. Emits 64-bit (d2bits<<32)|gidx candidates.
// ---------------------------------------------------------------------------
__global__ __launch_bounds__(P1T) void knn_pass1(const float* __restrict__ z)
{
    __shared__ __align__(16) float sPd[TS * DD];   // dim-major tile [d][j]
    __shared__ float sN[TS];

    int tid   = threadIdx.x;
    int q     = blockIdx.x * P1T + tid;
    int chunk = blockIdx.y;
    int cs    = chunk * CHUNK;

    // query -> packed broadcast pairs qp[d] = (q_d, q_d)
    unsigned long long qp[DD];
    float qn2 = 0.f;
    {
        const float2* zr = (const float2*)(z + (size_t)q * ZLD);
#pragma unroll
        for (int i = 0; i < 32; i++) {
            float2 v = zr[i];
            qn2 = fmaf(v.x, v.x, qn2);
            qn2 = fmaf(v.y, v.y, qn2);
            PACK2(qp[2 * i],     v.x, v.x);
            PACK2(qp[2 * i + 1], v.y, v.y);
        }
    }

    unsigned keys[KEEP];
    float    d2e[KEEP];
#pragma unroll
    for (int i = 0; i < KEEP; i++) { keys[i] = 0xFFFFFFFFu; d2e[i] = CUDART_INF_F; }

    // 13 tiles of 64 cover [cs, cs+832); padded global makes overflow benign
    for (int tt = 0; tt < 13; tt++) {
        int t0 = cs + tt * TS;
        __syncthreads();
        // load tile dim-major (coalesced float4, conflict-free)
        for (int i = tid; i < TS * 16; i += P1T) {
            int d = i >> 4, g = i & 15;
            ((float4*)sPd)[d * 16 + g] =
                ((const float4*)(g_dataT + (size_t)d * PADP + t0))[g];
        }
        if (tid < TS) sN[tid] = g_pn2[t0 + tid];
        __syncthreads();

        int lbase = t0 - cs;
        for (int j0 = 0; j0 < TS; j0 += 8) {
            unsigned long long a0 = 0ULL, a1 = 0ULL, a2 = 0ULL, a3 = 0ULL;
#pragma unroll
            for (int d = 0; d < DD; d++) {
                const ulonglong2* pp = (const ulonglong2*)(sPd + (d << 6) + j0);
                ulonglong2 v0 = pp[0];
                ulonglong2 v1 = pp[1];
                FMA2(a0, qp[d], v0.x);
                FMA2(a1, qp[d], v0.y);
                FMA2(a2, qp[d], v1.x);
                FMA2(a3, qp[d], v1.y);
            }
            float dots[8];
            UNPK2(dots[0], dots[1], a0);
            UNPK2(dots[2], dots[3], a1);
            UNPK2(dots[4], dots[5], a2);
            UNPK2(dots[6], dots[7], a3);
#pragma unroll
            for (int e = 0; e < 8; e++) {
                float s0 = qn2 + sN[j0 + e];
                float d2 = fmaf(-2.f, dots[e], s0);
                d2 = fmaxf(d2, 0.f);
                unsigned key = (__float_as_uint(d2) & 0xFFFFF800u) |
                               (unsigned)(lbase + j0 + e);
                if (key < keys[KEEP - 1]) {
                    unsigned ik = key; float id = d2;
#pragma unroll
                    for (int i = 0; i < KEEP; i++) {
                        if (ik < keys[i]) {
                            unsigned tk = keys[i]; keys[i] = ik; ik = tk;
                            float    td = d2e[i];  d2e[i]  = id; id = td;
                        }
                    }
                }
            }
        }
    }

    unsigned long long* outc = g_cand + (size_t)q * CAND + chunk * KEEP;
#pragma unroll
    for (int i = 0; i < KEEP; i++) {
        unsigned gidx = (unsigned)cs + (keys[i] & 0x7FFu);
        outc[i] = ((unsigned long long)__float_as_uint(d2e[i]) << 32) | gidx;
    }
}

// ---------------------------------------------------------------------------
// Kernel 3: pass 2 — barrier-light exact top-20 over 896 candidates,
// weights, u_t, cos_sim + L2 -> out cols 64,65.
// ---------------------------------------------------------------------------
__global__ __launch_bounds__(256) void knn_pass2(
    const float* __restrict__ vel, float* __restrict__ out)
{
    __shared__ unsigned long long sA[7 * KK];
    __shared__ float sdist[KK];
    __shared__ float swgt[KK];
    __shared__ int   sidx[KK];
    __shared__ float s_wsum;
    __shared__ float pr_ux[DD], pr_uu[DD], pr_xx[DD], pr_l2[DD];

    int q   = blockIdx.x;
    int tid = threadIdx.x;
    int wid = tid >> 5;
    int lane = tid & 31;
    const unsigned long long UMAX = ~0ULL;

    // register-resident candidates: warps 0..6 x 128 each = 896 (coalesced)
    unsigned long long kr[4];
    if (wid < 7) {
        const unsigned long long* src = g_cand + (size_t)q * CAND + wid * 128 + lane;
#pragma unroll
        for (int i = 0; i < 4; i++) kr[i] = src[32 * i];
    } else {
#pragma unroll
        for (int i = 0; i < 4; i++) kr[i] = UMAX;
    }

    // stage A: each of 7 warps selects its local top-20 (no block barriers)
    if (wid < 7) {
        for (int r = 0; r < KK; r++) {
            unsigned long long m0 = kr[0] < kr[1] ? kr[0] : kr[1];
            unsigned long long m1 = kr[2] < kr[3] ? kr[2] : kr[3];
            unsigned long long m = m0 < m1 ? m0 : m1;
#pragma unroll
            for (int o = 16; o > 0; o >>= 1) {
                unsigned long long v = __shfl_xor_sync(0xffffffffu, m, o);
                if (v < m) m = v;
            }
#pragma unroll
            for (int i = 0; i < 4; i++) if (kr[i] == m) kr[i] = UMAX;
            if (lane == 0) sA[wid * KK + r] = m;
        }
    }
    __syncthreads();

    // stage B: warp 0 merges 140 keys -> global top-20
    if (wid == 0) {
        unsigned long long kb[5];
#pragma unroll
        for (int i = 0; i < 5; i++) {
            int j = lane + 32 * i;
            kb[i] = (j < 7 * KK) ? sA[j] : UMAX;
        }
        for (int r = 0; r < KK; r++) {
            unsigned long long m = kb[0];
#pragma unroll
            for (int i = 1; i < 5; i++) if (kb[i] < m) m = kb[i];
#pragma unroll
            for (int o = 16; o > 0; o >>= 1) {
                unsigned long long v = __shfl_xor_sync(0xffffffffu, m, o);
                if (v < m) m = v;
            }
#pragma unroll
            for (int i = 0; i < 5; i++) if (kb[i] == m) kb[i] = UMAX;
            if (lane == 0) {
                float d2 = __uint_as_float((unsigned)(m >> 32));
                sdist[r] = sqrtf(fmaxf(d2, 1e-30f));
                sidx[r]  = (int)(m & 0xFFFFFFFFu);
            }
        }
    }
    __syncthreads();

    // weights
    if (tid < KK) {
        float h = fmaxf(sdist[KK - 1], 1e-12f);
        float dd = sdist[tid];
        swgt[tid] = expf(-(dd * dd) / (2.f * h * h));
    }
    __syncthreads();
    if (tid == 0) {
        float s = 0.f;
        for (int i = 0; i < KK; i++) s += swgt[i];
        s_wsum = s + 1e-12f;
    }
    __syncthreads();

    // u_t and metrics
    if (tid < DD) {
        float u = 0.f;
#pragma unroll
        for (int i = 0; i < KK; i++)
            u = fmaf(swgt[i], vel[(size_t)sidx[i] * DD + tid], u);
        u *= (1.f / s_wsum);
        float xd = out[(size_t)q * ZLD + tid];
        pr_ux[tid] = u * xd;
        pr_uu[tid] = u * u;
        pr_xx[tid] = xd * xd;
        float dfe = u - xd;
        pr_l2[tid] = dfe * dfe;
    }
    __syncthreads();
    if (tid == 0) {
        float ux = 0.f, uu = 0.f, xx = 0.f, l2 = 0.f;
        for (int d = 0; d < DD; d++) {
            ux += pr_ux[d]; uu += pr_uu[d]; xx += pr_xx[d]; l2 += pr_l2[d];
        }
        float nu = fmaxf(sqrtf(uu), 1e-8f);
        float nx = fmaxf(sqrtf(xx), 1e-8f);
        out[(size_t)q * ZLD + 64] = 1.f - ux / (nu * nx);
        out[(size_t)q * ZLD + 65] = l2;
    }
}

// ---------------------------------------------------------------------------
extern "C" void kernel_launch(void* const* d_in, const int* in_sizes, int n_in,
                              void* d_out, int out_size)
{
    const float* t    = (const float*)d_in[0];
    const float* z    = (const float*)d_in[1];
    const float* data = (const float*)d_in[2];
    const float* vel  = (const float*)d_in[3];
    const float* W1   = (const float*)d_in[4];
    const float* b1   = (const float*)d_in[5];
    const float* W2   = (const float*)d_in[6];
    const float* b2   = (const float*)d_in[7];
    float* out = (float*)d_out;

    tr_kernel<<<PADP / 64, 256>>>(data);
    pn2_kernel<<<(PADP + 255) / 256, 256>>>(data);
    mlp_kernel<<<NB / 8, 256>>>(z, t, W1, b1, W2, b2, out);
    knn_pass1<<<dim3(NB / P1T, NCH), P1T>>>(z);
    knn_pass2<<<NB, 256>>>(vel, out);
}